// round 17
// baseline (speedup 1.0000x reference)
#include <cuda_runtime.h>
#include <math.h>

#define POOL 7
#define ROI_SCALE 0.0625f
#define B_  4
#define C_  256
#define H_  64
#define W_  64
#define POP 51   // smem pool pitch (odd -> conflict-free STS across ch rows)

// Channels-last scratch: featT[b][y][x][c]
__device__ float g_featT[B_ * H_ * W_ * C_];

// Tiled transpose: feat[b][c][hw] (256 x 4096) -> featT[b][hw][c]
__global__ __launch_bounds__(256)
void transpose_kernel(const float* __restrict__ feat) {
    __shared__ float tile[32][33];
    int tx = threadIdx.x, ty = threadIdx.y;       // block (32, 8)
    int hw0 = blockIdx.x * 32;
    int c0  = blockIdx.y * 32;
    int b   = blockIdx.z;

    const float* src = feat + (unsigned)(b * C_ * H_ * W_);
    #pragma unroll
    for (int j = 0; j < 4; ++j) {
        int c = c0 + ty + j * 8;
        tile[ty + j * 8][tx] = src[c * (H_ * W_) + hw0 + tx];
    }
    __syncthreads();
    float* dst = g_featT + (unsigned)(b * H_ * W_ * C_);
    #pragma unroll
    for (int j = 0; j < 4; ++j) {
        int hw = hw0 + ty + j * 8;
        dst[hw * C_ + c0 + tx] = tile[tx][ty + j * 8];
    }
}

// grid = (C_/32, N). Block = (roi n, 32-channel slice). Thread 0 decodes ROI
// geometry into smem. Warp w (w<7) handles row-bin ph=w: for each pw, direct
// max over the bin's cells; lane = channel -> every LDG is one coalesced
// 128B wavefront. Results staged in smem, written out coalesced.
__global__ __launch_bounds__(256)
void roipool_kernel(const float* __restrict__ rois,
                    float* __restrict__ out,
                    int N, int write_bid) {
    __shared__ float po[32][POP];  // [ch][49 bins]
    __shared__ int g[10];          // b,px,py,qx, lenx,leny, psx,psy, pad0x,pad0y

    int n = blockIdx.y;

    // Fused second output of the reference tuple: batch ids as floats.
    if (write_bid && blockIdx.x == 0 && blockIdx.y == 0 && threadIdx.x < N) {
        out[N * C_ * POOL * POOL + threadIdx.x] =
            (float)((int)rois[threadIdx.x * 5]);
    }

    if (threadIdx.x == 0) {
        const float* r = rois + n * 5;
        // jnp.round = round-half-to-even = __float2int_rn
        int px = __float2int_rn(r[1] * ROI_SCALE);
        int py = __float2int_rn(r[2] * ROI_SCALE);
        int qx = __float2int_rn(r[3] * ROI_SCALE);
        int qy = __float2int_rn(r[4] * ROI_SCALE);
        int lenx = max(qx - px + 1, 1);
        int leny = max(qy - py + 1, 1);
        int psx  = (lenx + POOL - 1) / POOL;
        int psy  = (leny + POOL - 1) / POOL;
        g[0] = (int)r[0];
        g[1] = px; g[2] = py; g[3] = qx;
        g[4] = lenx; g[5] = leny;
        g[6] = psx; g[7] = psy;
        g[8] = (psx * POOL - lenx) / 2;
        g[9] = (psy * POOL - leny) / 2;
    }
    __syncthreads();

    int warp = threadIdx.x >> 5;
    int lane = threadIdx.x & 31;

    if (warp < POOL) {
        int ph = warp;
        int px = g[1], py = g[2];
        int lenx = g[4], leny = g[5], psx = g[6], psy = g[7];
        int pad0x = g[8], pad0y = g[9];

        int ys = max(0, ph * psy - pad0y);
        int ye = min(leny - 1, (ph + 1) * psy - 1 - pad0y);
        bool pady = (ph * psy < pad0y) | ((ph + 1) * psy > pad0y + leny);
        bool rows_empty = ys > ye;

        // lane's channel pointer at ROI origin (py, px)
        const float* bp = g_featT
            + (unsigned)(g[0] * H_ * W_ * C_)
            + (unsigned)((py * W_ + px) * C_) + blockIdx.x * 32 + lane;

        for (int pw = 0; pw < POOL; ++pw) {
            int xs = max(0, pw * psx - pad0x);
            int xe = min(lenx - 1, (pw + 1) * psx - 1 - pad0x);
            bool padx = (pw * psx < pad0x) | ((pw + 1) * psx > pad0x + lenx);

            float m;
            if (rows_empty || xs > xe) {
                m = 0.0f;                 // fully zero-padded bin
            } else {
                m = -INFINITY;
                const float* rowp = bp + (ys * W_ + xs) * C_;
                for (int y = ys; y <= ye; ++y) {
                    const float* p = rowp;
                    int x = xs;
                    #pragma unroll 2
                    for (; x + 1 <= xe; x += 2) {   // 2 loads in flight
                        float v0 = __ldg(p);
                        float v1 = __ldg(p + C_);
                        m = fmaxf(m, fmaxf(v0, v1));
                        p += 2 * C_;
                    }
                    if (x <= xe) m = fmaxf(m, __ldg(p));
                    rowp += W_ * C_;
                }
                if (padx | pady) m = fmaxf(m, 0.0f);
            }
            po[lane][ph * POOL + pw] = m;
        }
    }
    __syncthreads();

    // coalesced write: block span = out[n][cg*32 .. +32][49] (1568 floats)
    int base = (n * C_ + blockIdx.x * 32) * (POOL * POOL);
    for (int e = threadIdx.x; e < 32 * POOL * POOL; e += 256) {
        int ch = e / (POOL * POOL);
        int bin = e - ch * (POOL * POOL);
        out[base + e] = po[ch][bin];
    }
}

extern "C" void kernel_launch(void* const* d_in, const int* in_sizes, int n_in,
                              void* d_out, int out_size) {
    const float* feat = (const float*)d_in[0];
    const float* rois = (const float*)d_in[1];
    float* out = (float*)d_out;

    int N = in_sizes[1] / 5;
    int total = N * C_ * POOL * POOL;
    int write_bid = (out_size >= total + N) ? 1 : 0;

    dim3 tgrid(H_ * W_ / 32, C_ / 32, B_);       // 128 x 8 x 4
    transpose_kernel<<<tgrid, dim3(32, 8)>>>(feat);

    dim3 pgrid(C_ / 32, N);                       // 8 x N
    roipool_kernel<<<pgrid, 256>>>(rois, out, N, write_bid);
}